// round 14
// baseline (speedup 1.0000x reference)
#include <cuda_runtime.h>
#include <cuda_bf16.h>
#include <stdint.h>

// ---------------- problem constants ----------------
#define MAXN 50000
#define MAXE 1600000

// ---------------- device scratch ----------------
__device__ int   g_is64;
__device__ int   g_deg[MAXN];          // invariant: all-zero at kernel_launch entry
__device__ int   g_rowptr[MAXN + 1];
__device__ int   g_cursor[MAXN];
__device__ int   g_bsum[64];
__device__ unsigned short g_col[MAXE]; // N < 65536 -> 16-bit column indices
__device__ __nv_bfloat16 g_xh[MAXN * 32];            // bf16 copy of x for agg1
__device__ float g_xa[MAXN * 64];
__device__ float g_W1[64 * 384];
__device__ float g_W2[192 * 384];
__device__ float g_h1[(size_t)MAXN * 192];
__device__ float g_lin[(size_t)MAXN * 128];          // relu(fc21) part of block 2
__device__ float g_cprod[(size_t)MAXN * 64];         // relu(fc22)*relu(fc23)
__device__ __nv_bfloat16 g_m2h[(size_t)MAXN * 128];  // raw conv21 messages (bf16)
__device__ float g_h2[(size_t)MAXN * 192];

// ---------------- index decode (int64 vs int32) ----------
__device__ __forceinline__ int ld_index_r(const void* p, long long i, int is64) {
    if (is64) return (int)((const long long*)p)[i];
    return ((const int*)p)[i];
}

// Fused init: dtype detect, weight packs, x -> bf16 convert, AND histogram.
// deg[] is all-zero on entry (static zero-init on first call; k_scan_a
// re-zeroes after consuming on every call), so hist can run here directly.
__global__ void k_init(const unsigned int* __restrict__ ei,
                       const float* __restrict__ x,
                       const float* __restrict__ fc11, const float* __restrict__ conv11,
                       const float* __restrict__ fc12, const float* __restrict__ fc13,
                       const float* __restrict__ fc21, const float* __restrict__ conv21,
                       const float* __restrict__ fc22, const float* __restrict__ fc23,
                       int N, int E) {
    int i = blockIdx.x * blockDim.x + threadIdx.x;
    if (i == 0) {
        int ok = 1;
        for (int q = 1; q < 64; q += 2)
            if (ei[q] != 0u) ok = 0;
        g_is64 = ok;   // for later kernels
    }
    if (i < E) {
        // local dtype detect (L1-broadcast loads; false positive ~4e-10)
        int is64 = (ei[1] == 0u && ei[3] == 0u) ? 1 : 0;
        int d = ld_index_r(ei, (long long)E + i, is64);
        atomicAdd(&g_deg[d], 1);
    }
    if (i < N * 32) g_xh[i] = __float2bfloat16(x[i]);
    if (i < 64 * 384) {
        int k = i / 384, m = i % 384;
        int s = m >> 7, l = m & 127, half = l >> 6, c = l & 63;
        float v = 0.f;
        if (s < 2) {
            int ch = s * 64 + c;
            if (half == 0) { if (k < 32) v = fc11[k * 128 + ch]; }
            else           { if (k >= 32) v = conv11[(k - 32) * 128 + ch]; }
        } else {
            if (k < 32) v = half ? fc13[k * 64 + c] : fc12[k * 64 + c];
        }
        g_W1[i] = v;
    }
    if (i < 192 * 384) {
        int k = i / 384, m = i % 384;
        int s = m >> 7, l = m & 127, half = l >> 6, c = l & 63;
        float v;
        if (s < 2) {
            int ch = s * 64 + c;
            v = half ? conv21[k * 128 + ch] : fc21[k * 128 + ch];
        } else {
            v = half ? fc23[k * 64 + c] : fc22[k * 64 + c];
        }
        g_W2[i] = v;
    }
}

// ---------------- multi-block scan (R10-proven) ----------------
// Reads deg and RE-ZEROES it (maintains the entry invariant for next run).
__global__ void k_scan_a(int n) {
    __shared__ int wsum[32];
    int tid = threadIdx.x;
    int i = blockIdx.x * 1024 + tid;
    int lane = tid & 31, warp = tid >> 5;
    int v = 0;
    if (i < n) { v = g_deg[i]; g_deg[i] = 0; }
    int s = v;
#pragma unroll
    for (int off = 1; off < 32; off <<= 1) {
        int t = __shfl_up_sync(0xffffffffu, s, off);
        if (lane >= off) s += t;
    }
    if (lane == 31) wsum[warp] = s;
    __syncthreads();
    if (warp == 0) {
        int w = wsum[lane];
        int ws = w;
#pragma unroll
        for (int off = 1; off < 32; off <<= 1) {
            int t = __shfl_up_sync(0xffffffffu, ws, off);
            if (lane >= off) ws += t;
        }
        wsum[lane] = ws - w;
        if (lane == 31) g_bsum[blockIdx.x] = ws;
    }
    __syncthreads();
    if (i < n) g_rowptr[i] = (s - v) + wsum[warp];
}

// add prefix of block sums (computed once per block, smem broadcast), init cursor.
__global__ void k_scan_c(int n, int E) {
    __shared__ int soff;
    int i = blockIdx.x * blockDim.x + threadIdx.x;
    if (threadIdx.x == 0) {
        int blk = (blockIdx.x * blockDim.x) >> 10;
        int off = 0;
        for (int b = 0; b < blk; b++) off += g_bsum[b];
        soff = off;
    }
    __syncthreads();
    if (i < n) {
        int r = g_rowptr[i] + soff;
        g_rowptr[i] = r;
        g_cursor[i] = r;
    }
    if (i == 0) g_rowptr[n] = E;
}

// simple per-edge fill (R10-proven; atomic-throughput-bound ~27us floor)
__global__ void k_fill(const void* ei, int E) {
    int i = blockIdx.x * blockDim.x + threadIdx.x;
    if (i < E) {
        int is64 = g_is64;
        int s = ld_index_r(ei, i, is64);
        int d = ld_index_r(ei, (long long)E + i, is64);
        int p = atomicAdd(&g_cursor[d], 1);
        g_col[p] = (unsigned short)s;
    }
}

// agg1 + xa pack. Warp per node; HALF-WARP edge split (R13-proven):
__global__ void k_agg1(const float* __restrict__ x, int N) {
    int w = (blockIdx.x * blockDim.x + threadIdx.x) >> 5;
    int lane = threadIdx.x & 31;
    if (w >= N) return;
    g_xa[w * 64 + lane] = x[w * 32 + lane];
    int ln = lane & 15;
    int half = lane >> 4;
    int e0 = g_rowptr[w], e1 = g_rowptr[w + 1];
    float a0 = 0.f, a1 = 0.f;
    for (int e = e0 + 2 * half; e < e1; e += 4) {
        int s0 = g_col[e];
        float2 f0 = __bfloat1622float2(*(const __nv_bfloat162*)(g_xh + s0 * 32 + ln * 2));
        a0 += f0.x; a1 += f0.y;
        if (e + 1 < e1) {
            int s1 = g_col[e + 1];
            float2 f1 = __bfloat1622float2(*(const __nv_bfloat162*)(g_xh + s1 * 32 + ln * 2));
            a0 += f1.x; a1 += f1.y;
        }
    }
    a0 += __shfl_xor_sync(0xffffffffu, a0, 16);
    a1 += __shfl_xor_sync(0xffffffffu, a1, 16);
    if (lane < 16)
        *(float2*)(g_xa + (size_t)w * 64 + 32 + ln * 2) = make_float2(a0, a1);
}

// ---------------- TF32 tensor-core GEMM w/ fused epilogue ----------------
__device__ __forceinline__ uint32_t f2tf32(float f) {
    uint32_t u;
    asm("cvt.rna.tf32.f32 %0, %1;" : "=r"(u) : "f"(f));
    return u;
}

__device__ __forceinline__ void mma_tf32(float& d0, float& d1, float& d2, float& d3,
                                         uint32_t a0, uint32_t a1, uint32_t a2, uint32_t a3,
                                         uint32_t b0, uint32_t b1) {
    asm volatile("mma.sync.aligned.m16n8k8.row.col.f32.tf32.tf32.f32 "
                 "{%0,%1,%2,%3},{%4,%5,%6,%7},{%8,%9},{%0,%1,%2,%3};\n"
                 : "+f"(d0), "+f"(d1), "+f"(d2), "+f"(d3)
                 : "r"(a0), "r"(a1), "r"(a2), "r"(a3), "r"(b0), "r"(b1));
}

// C[N,384] = A[N,K] @ W[K,384], double-buffered smem (1 sync / k-chunk).
// MODE 1: epilogue -> g_h1; MODE 2: epilogue -> g_lin / g_m2h / g_cprod
template <int MODE>
__global__ __launch_bounds__(256, 2) void k_gemm_tc(
    int N,
    const float* __restrict__ bL1, const float* __restrict__ bR1,
    const float* __restrict__ bL2, const float* __restrict__ bR2,
    const float* __restrict__ bng, const float* __restrict__ bnb,
    const float* __restrict__ bnm, const float* __restrict__ bnv) {
    constexpr int K = (MODE == 1) ? 64 : 192;
    constexpr int NK = K / 8;
    const float* __restrict__ A = (MODE == 1) ? g_xa : g_h1;
    const float* __restrict__ W = (MODE == 1) ? g_W1 : g_W2;

    __shared__ uint32_t As[2][128 * 12];
    __shared__ uint32_t Ws[2][128 * 12];

    const int rowBase = blockIdx.x * 128;
    const int s = blockIdx.y;          // col slice 0..2
    const int colBase = s * 128;
    const int tid = threadIdx.x;
    const int warp = tid >> 5, lane = tid & 31;
    const int wm = warp >> 2, wn = warp & 3;
    const int gq = lane >> 2, tq = lane & 3;

    float acc[4][4][4];
#pragma unroll
    for (int i = 0; i < 4; i++)
#pragma unroll
        for (int j = 0; j < 4; j++)
#pragma unroll
            for (int c = 0; c < 4; c++) acc[i][j][c] = 0.f;

    const int ar = tid >> 1, ah = tid & 1;
    const int wc = tid & 127, wkp = tid >> 7;
    int gr = rowBase + ar;
    if (gr >= N) gr = N - 1;
    const float* Arow = A + (size_t)gr * K + ah * 4;
    const float* Wcol = W + colBase + wc;

    // prologue: stage chunk 0 -> buffer 0
    {
        float4 av = *(const float4*)(Arow);
        uint32_t* ad = &As[0][ar * 12 + ah * 4];
        ad[0] = f2tf32(av.x); ad[1] = f2tf32(av.y);
        ad[2] = f2tf32(av.z); ad[3] = f2tf32(av.w);
#pragma unroll
        for (int i = 0; i < 4; i++)
            Ws[0][wc * 12 + wkp * 4 + i] = f2tf32(Wcol[(size_t)(wkp * 4 + i) * 384]);
    }
    __syncthreads();

    for (int kc = 0; kc < NK; kc++) {
        const int cur = kc & 1;
        float4 av;
        float wv[4];
        const bool more = (kc + 1 < NK);
        if (more) {
            av = *(const float4*)(Arow + (kc + 1) * 8);
#pragma unroll
            for (int i = 0; i < 4; i++)
                wv[i] = Wcol[(size_t)((kc + 1) * 8 + wkp * 4 + i) * 384];
        }

        uint32_t af[4][4], bf[4][2];
#pragma unroll
        for (int i = 0; i < 4; i++) {
            int m0 = wm * 64 + i * 16;
            af[i][0] = As[cur][(m0 + gq) * 12 + tq];
            af[i][1] = As[cur][(m0 + gq + 8) * 12 + tq];
            af[i][2] = As[cur][(m0 + gq) * 12 + tq + 4];
            af[i][3] = As[cur][(m0 + gq + 8) * 12 + tq + 4];
        }
#pragma unroll
        for (int j = 0; j < 4; j++) {
            int n0 = ((j < 2) ? 0 : 64) + wn * 16 + (j & 1) * 8;
            bf[j][0] = Ws[cur][(n0 + gq) * 12 + tq];
            bf[j][1] = Ws[cur][(n0 + gq) * 12 + tq + 4];
        }
#pragma unroll
        for (int i = 0; i < 4; i++)
#pragma unroll
            for (int j = 0; j < 4; j++)
                mma_tf32(acc[i][j][0], acc[i][j][1], acc[i][j][2], acc[i][j][3],
                         af[i][0], af[i][1], af[i][2], af[i][3],
                         bf[j][0], bf[j][1]);

        if (more) {
            uint32_t* ad = &As[cur ^ 1][ar * 12 + ah * 4];
            ad[0] = f2tf32(av.x); ad[1] = f2tf32(av.y);
            ad[2] = f2tf32(av.z); ad[3] = f2tf32(av.w);
#pragma unroll
            for (int i = 0; i < 4; i++)
                Ws[cur ^ 1][wc * 12 + wkp * 4 + i] = f2tf32(wv[i]);
        }
        __syncthreads();
    }

    // fused epilogue: pairs are (acc[i][j][*], acc[i][j+2][*]) for j=0,1
#pragma unroll
    for (int i = 0; i < 4; i++) {
#pragma unroll
        for (int j = 0; j < 2; j++) {
            int l = wn * 16 + j * 8 + tq * 2;  // local col in [0,64)
#pragma unroll
            for (int p = 0; p < 2; p++) {
                int n = rowBase + wm * 64 + i * 16 + gq + p * 8;
                if (n >= N) continue;
                float o0, o1;
                if (s < 2) {
                    int ch = s * 64 + l;
                    float L0 = acc[i][j][p * 2 + 0], L1 = acc[i][j][p * 2 + 1];
                    float R0 = acc[i][j + 2][p * 2 + 0], R1 = acc[i][j + 2][p * 2 + 1];
                    if (MODE == 1) {
                        float v0 = fmaxf(L0 + __ldg(&bL1[ch]), 0.f) +
                                   fmaxf(R0 + __ldg(&bR1[ch]), 0.f);
                        float v1 = fmaxf(L1 + __ldg(&bL1[ch + 1]), 0.f) +
                                   fmaxf(R1 + __ldg(&bR1[ch + 1]), 0.f);
                        o0 = __ldg(&bng[ch]) * (v0 - __ldg(&bnm[ch])) *
                                 rsqrtf(__ldg(&bnv[ch]) + 1e-5f) + __ldg(&bnb[ch]);
                        o1 = __ldg(&bng[ch + 1]) * (v1 - __ldg(&bnm[ch + 1])) *
                                 rsqrtf(__ldg(&bnv[ch + 1]) + 1e-5f) + __ldg(&bnb[ch + 1]);
                        *(float2*)(g_h1 + (size_t)n * 192 + ch) = make_float2(o0, o1);
                    } else {
                        float r0 = fmaxf(L0 + __ldg(&bL1[ch]), 0.f);
                        float r1 = fmaxf(L1 + __ldg(&bL1[ch + 1]), 0.f);
                        *(float2*)(g_lin + (size_t)n * 128 + ch) = make_float2(r0, r1);
                        *(__nv_bfloat162*)(g_m2h + (size_t)n * 128 + ch) =
                            __floats2bfloat162_rn(R0, R1);
                    }
                } else {
                    float L0 = acc[i][j][p * 2 + 0], L1 = acc[i][j][p * 2 + 1];
                    float R0 = acc[i][j + 2][p * 2 + 0], R1 = acc[i][j + 2][p * 2 + 1];
                    float v0 = fmaxf(L0 + __ldg(&bL2[l]), 0.f) *
                               fmaxf(R0 + __ldg(&bR2[l]), 0.f);
                    float v1 = fmaxf(L1 + __ldg(&bL2[l + 1]), 0.f) *
                               fmaxf(R1 + __ldg(&bR2[l + 1]), 0.f);
                    if (MODE == 1) {
                        int ch = 128 + l;
                        o0 = __ldg(&bng[ch]) * (v0 - __ldg(&bnm[ch])) *
                                 rsqrtf(__ldg(&bnv[ch]) + 1e-5f) + __ldg(&bnb[ch]);
                        o1 = __ldg(&bng[ch + 1]) * (v1 - __ldg(&bnm[ch + 1])) *
                                 rsqrtf(__ldg(&bnv[ch + 1]) + 1e-5f) + __ldg(&bnb[ch + 1]);
                        *(float2*)(g_h1 + (size_t)n * 192 + ch) = make_float2(o0, o1);
                    } else {
                        *(float2*)(g_cprod + (size_t)n * 64 + l) = make_float2(v0, v1);
                    }
                }
            }
        }
    }
}

// Fused agg2+ep2, 2 warps per node for 2x memory-level parallelism.
// Warp h of node w owns channels [h*64, h*64+64): lane loads one 4-byte word
// (2 bf16) per edge. Channel accumulation order identical to before ->
// bit-identical results. cprod channels handled by warp h==0.
__global__ void k_agg2_ep2(const float* __restrict__ conv21_b,
                           const float* __restrict__ gg, const float* __restrict__ bb,
                           const float* __restrict__ mm, const float* __restrict__ vv,
                           int N) {
    int gw = (blockIdx.x * blockDim.x + threadIdx.x) >> 5;
    int w = gw >> 1;
    int h = gw & 1;
    int lane = threadIdx.x & 31;
    if (w >= N) return;
    int c0 = h * 64 + lane * 2;   // this lane's channel pair
    int e0 = g_rowptr[w], e1 = g_rowptr[w + 1];
    float a0 = 0.f, a1 = 0.f;
    int e = e0;
    for (; e + 4 <= e1; e += 4) {
        int s0 = g_col[e], s1 = g_col[e + 1], s2 = g_col[e + 2], s3 = g_col[e + 3];
        uint32_t u0 = *(const uint32_t*)(g_m2h + (size_t)s0 * 128 + c0);
        uint32_t u1 = *(const uint32_t*)(g_m2h + (size_t)s1 * 128 + c0);
        uint32_t u2 = *(const uint32_t*)(g_m2h + (size_t)s2 * 128 + c0);
        uint32_t u3 = *(const uint32_t*)(g_m2h + (size_t)s3 * 128 + c0);
        float2 f0 = __bfloat1622float2(*(__nv_bfloat162*)&u0);
        float2 f1 = __bfloat1622float2(*(__nv_bfloat162*)&u1);
        float2 f2 = __bfloat1622float2(*(__nv_bfloat162*)&u2);
        float2 f3 = __bfloat1622float2(*(__nv_bfloat162*)&u3);
        a0 += f0.x; a1 += f0.y;
        a0 += f1.x; a1 += f1.y;
        a0 += f2.x; a1 += f2.y;
        a0 += f3.x; a1 += f3.y;
    }
    for (; e < e1; e++) {
        int sc = g_col[e];
        uint32_t u = *(const uint32_t*)(g_m2h + (size_t)sc * 128 + c0);
        float2 f = __bfloat1622float2(*(__nv_bfloat162*)&u);
        a0 += f.x; a1 += f.y;
    }
    // epilogue for channel pair c0, c0+1
    float2 lb = *(const float2*)(g_lin + (size_t)w * 128 + c0);
    float2 cb = *(const float2*)(conv21_b + c0);
    float v0 = lb.x + fmaxf(a0 + cb.x, 0.f);
    float v1 = lb.y + fmaxf(a1 + cb.y, 0.f);
    float2 G = *(const float2*)(gg + c0);
    float2 B = *(const float2*)(bb + c0);
    float2 M = *(const float2*)(mm + c0);
    float2 V = *(const float2*)(vv + c0);
    float2 o;
    o.x = G.x * (v0 - M.x) * rsqrtf(V.x + 1e-5f) + B.x;
    o.y = G.y * (v1 - M.y) * rsqrtf(V.y + 1e-5f) + B.y;
    *(float2*)(g_h2 + (size_t)w * 192 + c0) = o;
    // cprod channels 128..191: warp h==0, lane handles pair 128 + lane*2
    if (h == 0) {
        int l = lane * 2, ch = 128 + l;
        float2 cp = *(const float2*)(g_cprod + (size_t)w * 64 + l);
        float2 G2 = *(const float2*)(gg + ch);
        float2 B2 = *(const float2*)(bb + ch);
        float2 M2 = *(const float2*)(mm + ch);
        float2 V2 = *(const float2*)(vv + ch);
        float2 o2;
        o2.x = G2.x * (cp.x - M2.x) * rsqrtf(V2.x + 1e-5f) + B2.x;
        o2.y = G2.y * (cp.y - M2.y) * rsqrtf(V2.y + 1e-5f) + B2.y;
        *(float2*)(g_h2 + (size_t)w * 192 + ch) = o2;
    }
}

// ---------------- fused pooling + head (batch is sorted) ----------------
__device__ __forceinline__ int lb_batch(const void* batch, int n, long long val) {
    int lo = 0, hi = n;
    while (lo < hi) {
        int mid = (lo + hi) >> 1;
        long long b = g_is64 ? ((const long long*)batch)[mid]
                             : (long long)((const int*)batch)[mid];
        if (b < val) lo = mid + 1; else hi = mid;
    }
    return lo;
}

__global__ void k_poolhead(const void* batch, int N,
                           const float* __restrict__ w2, const float* __restrict__ b2,
                           float* __restrict__ out) {
    int g = blockIdx.x;
    __shared__ int slo, shi;
    __shared__ float spool[384];
    __shared__ float cls[6][6];
    int tid = threadIdx.x;
    if (tid == 0) {
        slo = lb_batch(batch, N, (long long)g);
        shi = lb_batch(batch, N, (long long)g + 1);
    }
    __syncthreads();
    int lo = slo, hi = shi;
    float sum = 0.f, mx = -3.402823466e38f;
    for (int n = lo; n < hi; n++) {
        float v = g_h2[(size_t)n * 192 + tid];
        sum += v;
        mx = fmaxf(mx, v);
    }
    int cnt = hi - lo;
    spool[tid] = sum / fmaxf((float)cnt, 1.f);
    spool[192 + tid] = (cnt > 0) ? mx : 0.f;
    __syncthreads();

    float p[6] = {0.f, 0.f, 0.f, 0.f, 0.f, 0.f};
#pragma unroll
    for (int h = 0; h < 2; h++) {
        int kk = tid + h * 192;
        float gv = spool[kk];
#pragma unroll
        for (int j = 0; j < 6; j++) p[j] += gv * __ldg(&w2[kk * 6 + j]);
    }
    int lane = tid & 31, warp = tid >> 5;
#pragma unroll
    for (int off = 16; off; off >>= 1)
#pragma unroll
        for (int j = 0; j < 6; j++) p[j] += __shfl_xor_sync(0xffffffffu, p[j], off);
    if (lane == 0)
#pragma unroll
        for (int j = 0; j < 6; j++) cls[j][warp] = p[j];
    __syncthreads();
    if (tid == 0) {
        float v[6];
        float mxv = -3.402823466e38f;
#pragma unroll
        for (int j = 0; j < 6; j++) {
            float acc = b2[j];
#pragma unroll
            for (int q = 0; q < 6; q++) acc += cls[j][q];
            v[j] = acc;
            mxv = fmaxf(mxv, acc);
        }
        float ssum = 0.f;
#pragma unroll
        for (int j = 0; j < 6; j++) ssum += expf(v[j] - mxv);
        float lse = mxv + logf(ssum);
#pragma unroll
        for (int j = 0; j < 6; j++) out[g * 6 + j] = v[j] - lse;
    }
}

// ---------------- launch ----------------
extern "C" void kernel_launch(void* const* d_in, const int* in_sizes, int n_in,
                              void* d_out, int out_size) {
    int base = (n_in >= 30) ? 4 : 3;
    const float* x        = (const float*)d_in[0];
    const void*  ei       = d_in[1];
    const void*  batch    = d_in[2];
    const float* fc11_w   = (const float*)d_in[base + 0];
    const float* fc11_b   = (const float*)d_in[base + 1];
    const float* conv11_w = (const float*)d_in[base + 2];
    const float* conv11_b = (const float*)d_in[base + 3];
    const float* fc12_w   = (const float*)d_in[base + 4];
    const float* fc12_b   = (const float*)d_in[base + 5];
    const float* fc13_w   = (const float*)d_in[base + 6];
    const float* fc13_b   = (const float*)d_in[base + 7];
    const float* bn1_g    = (const float*)d_in[base + 8];
    const float* bn1_b    = (const float*)d_in[base + 9];
    const float* bn1_m    = (const float*)d_in[base + 10];
    const float* bn1_v    = (const float*)d_in[base + 11];
    const float* fc21_w   = (const float*)d_in[base + 12];
    const float* fc21_b   = (const float*)d_in[base + 13];
    const float* conv21_w = (const float*)d_in[base + 14];
    const float* conv21_b = (const float*)d_in[base + 15];
    const float* fc22_w   = (const float*)d_in[base + 16];
    const float* fc22_b   = (const float*)d_in[base + 17];
    const float* fc23_w   = (const float*)d_in[base + 18];
    const float* fc23_b   = (const float*)d_in[base + 19];
    const float* bn2_g    = (const float*)d_in[base + 20];
    const float* bn2_b    = (const float*)d_in[base + 21];
    const float* bn2_m    = (const float*)d_in[base + 22];
    const float* bn2_v    = (const float*)d_in[base + 23];
    const float* fc2_w    = (const float*)d_in[base + 24];
    const float* fc2_b    = (const float*)d_in[base + 25];

    int N = in_sizes[0] / 32;
    int E = in_sizes[1] / 2;
    int G = out_size / 6;
    float* out = (float*)d_out;

    // fused init+hist, two-kernel scan, per-edge fill
    int initN = N * 32;
    if (initN < E) initN = E;
    if (initN < 192 * 384) initN = 192 * 384;
    k_init<<<(initN + 255) / 256, 256>>>((const unsigned int*)ei, x,
                                         fc11_w, conv11_w, fc12_w, fc13_w,
                                         fc21_w, conv21_w, fc22_w, fc23_w, N, E);
    int nb = (N + 1023) / 1024;
    k_scan_a<<<nb, 1024>>>(N);
    k_scan_c<<<(N + 255) / 256, 256>>>(N, E);
    k_fill<<<(E + 255) / 256, 256>>>(ei, E);

    // block 1
    k_agg1<<<(N * 32 + 255) / 256, 256>>>(x, N);
    dim3 gg((N + 127) / 128, 3);
    k_gemm_tc<1><<<gg, 256>>>(N, fc11_b, conv11_b, fc12_b, fc13_b,
                              bn1_g, bn1_b, bn1_m, bn1_v);

    // block 2
    k_gemm_tc<2><<<gg, 256>>>(N, fc21_b, conv21_b, fc22_b, fc23_b,
                              bn2_g, bn2_b, bn2_m, bn2_v);
    k_agg2_ep2<<<(N * 64 + 255) / 256, 256>>>(conv21_b, bn2_g, bn2_b, bn2_m, bn2_v, N);

    // fused pooling + head
    k_poolhead<<<G, 192>>>(batch, N, fc2_w, fc2_b, out);
}

// round 17
// speedup vs baseline: 1.0669x; 1.0669x over previous
#include <cuda_runtime.h>
#include <cuda_bf16.h>
#include <stdint.h>

// ---------------- problem constants ----------------
#define MAXN 50000
#define MAXE 1600000

// ---------------- device scratch ----------------
__device__ int   g_is64;
__device__ int   g_deg[MAXN];          // invariant: all-zero at kernel_launch entry
__device__ int   g_rowptr[MAXN + 1];
__device__ int   g_cursor[MAXN];
__device__ int   g_bsum[64];
__device__ unsigned short g_col[MAXE]; // N < 65536 -> 16-bit column indices
__device__ __nv_bfloat16 g_xh[MAXN * 32];            // bf16 copy of x for agg1
__device__ float g_xa[MAXN * 64];
__device__ float g_W1[64 * 384];
__device__ float g_W2[192 * 384];
__device__ float g_h1[(size_t)MAXN * 192];
__device__ float g_lin[(size_t)MAXN * 128];          // relu(fc21) part of block 2
__device__ float g_cprod[(size_t)MAXN * 64];         // relu(fc22)*relu(fc23)
__device__ __nv_bfloat16 g_m2h[(size_t)MAXN * 128];  // raw conv21 messages (bf16)
__device__ float g_h2[(size_t)MAXN * 192];

// ---------------- index decode (int64 vs int32) ----------
__device__ __forceinline__ int ld_index_r(const void* p, long long i, int is64) {
    if (is64) return (int)((const long long*)p)[i];
    return ((const int*)p)[i];
}

// Fused init: dtype detect, weight packs, x -> bf16 convert, AND histogram.
// deg[] is all-zero on entry (static zero-init on first call; k_scan_a
// re-zeroes after consuming on every call), so hist can run here directly.
__global__ void k_init(const unsigned int* __restrict__ ei,
                       const float* __restrict__ x,
                       const float* __restrict__ fc11, const float* __restrict__ conv11,
                       const float* __restrict__ fc12, const float* __restrict__ fc13,
                       const float* __restrict__ fc21, const float* __restrict__ conv21,
                       const float* __restrict__ fc22, const float* __restrict__ fc23,
                       int N, int E) {
    int i = blockIdx.x * blockDim.x + threadIdx.x;
    if (i == 0) {
        int ok = 1;
        for (int q = 1; q < 64; q += 2)
            if (ei[q] != 0u) ok = 0;
        g_is64 = ok;   // for later kernels
    }
    if (i < E) {
        // local dtype detect (L1-broadcast loads; false positive ~4e-10)
        int is64 = (ei[1] == 0u && ei[3] == 0u) ? 1 : 0;
        int d = ld_index_r(ei, (long long)E + i, is64);
        atomicAdd(&g_deg[d], 1);
    }
    if (i < N * 32) g_xh[i] = __float2bfloat16(x[i]);
    if (i < 64 * 384) {
        int k = i / 384, m = i % 384;
        int s = m >> 7, l = m & 127, half = l >> 6, c = l & 63;
        float v = 0.f;
        if (s < 2) {
            int ch = s * 64 + c;
            if (half == 0) { if (k < 32) v = fc11[k * 128 + ch]; }
            else           { if (k >= 32) v = conv11[(k - 32) * 128 + ch]; }
        } else {
            if (k < 32) v = half ? fc13[k * 64 + c] : fc12[k * 64 + c];
        }
        g_W1[i] = v;
    }
    if (i < 192 * 384) {
        int k = i / 384, m = i % 384;
        int s = m >> 7, l = m & 127, half = l >> 6, c = l & 63;
        float v;
        if (s < 2) {
            int ch = s * 64 + c;
            v = half ? conv21[k * 128 + ch] : fc21[k * 128 + ch];
        } else {
            v = half ? fc23[k * 64 + c] : fc22[k * 64 + c];
        }
        g_W2[i] = v;
    }
}

// ---------------- multi-block scan (R10-proven) ----------------
// Reads deg and RE-ZEROES it (maintains the entry invariant for next run).
__global__ void k_scan_a(int n) {
    __shared__ int wsum[32];
    int tid = threadIdx.x;
    int i = blockIdx.x * 1024 + tid;
    int lane = tid & 31, warp = tid >> 5;
    int v = 0;
    if (i < n) { v = g_deg[i]; g_deg[i] = 0; }
    int s = v;
#pragma unroll
    for (int off = 1; off < 32; off <<= 1) {
        int t = __shfl_up_sync(0xffffffffu, s, off);
        if (lane >= off) s += t;
    }
    if (lane == 31) wsum[warp] = s;
    __syncthreads();
    if (warp == 0) {
        int w = wsum[lane];
        int ws = w;
#pragma unroll
        for (int off = 1; off < 32; off <<= 1) {
            int t = __shfl_up_sync(0xffffffffu, ws, off);
            if (lane >= off) ws += t;
        }
        wsum[lane] = ws - w;
        if (lane == 31) g_bsum[blockIdx.x] = ws;
    }
    __syncthreads();
    if (i < n) g_rowptr[i] = (s - v) + wsum[warp];
}

// add prefix of block sums (computed once per block, smem broadcast), init cursor.
__global__ void k_scan_c(int n, int E) {
    __shared__ int soff;
    int i = blockIdx.x * blockDim.x + threadIdx.x;
    if (threadIdx.x == 0) {
        int blk = (blockIdx.x * blockDim.x) >> 10;
        int off = 0;
        for (int b = 0; b < blk; b++) off += g_bsum[b];
        soff = off;
    }
    __syncthreads();
    if (i < n) {
        int r = g_rowptr[i] + soff;
        g_rowptr[i] = r;
        g_cursor[i] = r;
    }
    if (i == 0) g_rowptr[n] = E;
}

// simple per-edge fill (R10-proven; atomic-throughput-bound ~27us floor)
__global__ void k_fill(const void* ei, int E) {
    int i = blockIdx.x * blockDim.x + threadIdx.x;
    if (i < E) {
        int is64 = g_is64;
        int s = ld_index_r(ei, i, is64);
        int d = ld_index_r(ei, (long long)E + i, is64);
        int p = atomicAdd(&g_cursor[d], 1);
        g_col[p] = (unsigned short)s;
    }
}

// agg1 + xa pack. Warp per node; HALF-WARP edge split (R13-proven):
__global__ void k_agg1(const float* __restrict__ x, int N) {
    int w = (blockIdx.x * blockDim.x + threadIdx.x) >> 5;
    int lane = threadIdx.x & 31;
    if (w >= N) return;
    g_xa[w * 64 + lane] = x[w * 32 + lane];
    int ln = lane & 15;
    int half = lane >> 4;
    int e0 = g_rowptr[w], e1 = g_rowptr[w + 1];
    float a0 = 0.f, a1 = 0.f;
    for (int e = e0 + 2 * half; e < e1; e += 4) {
        int s0 = g_col[e];
        float2 f0 = __bfloat1622float2(*(const __nv_bfloat162*)(g_xh + s0 * 32 + ln * 2));
        a0 += f0.x; a1 += f0.y;
        if (e + 1 < e1) {
            int s1 = g_col[e + 1];
            float2 f1 = __bfloat1622float2(*(const __nv_bfloat162*)(g_xh + s1 * 32 + ln * 2));
            a0 += f1.x; a1 += f1.y;
        }
    }
    a0 += __shfl_xor_sync(0xffffffffu, a0, 16);
    a1 += __shfl_xor_sync(0xffffffffu, a1, 16);
    if (lane < 16)
        *(float2*)(g_xa + (size_t)w * 64 + 32 + ln * 2) = make_float2(a0, a1);
}

// ---------------- TF32 tensor-core GEMM w/ fused epilogue ----------------
__device__ __forceinline__ uint32_t f2tf32(float f) {
    uint32_t u;
    asm("cvt.rna.tf32.f32 %0, %1;" : "=r"(u) : "f"(f));
    return u;
}

__device__ __forceinline__ void mma_tf32(float& d0, float& d1, float& d2, float& d3,
                                         uint32_t a0, uint32_t a1, uint32_t a2, uint32_t a3,
                                         uint32_t b0, uint32_t b1) {
    asm volatile("mma.sync.aligned.m16n8k8.row.col.f32.tf32.tf32.f32 "
                 "{%0,%1,%2,%3},{%4,%5,%6,%7},{%8,%9},{%0,%1,%2,%3};\n"
                 : "+f"(d0), "+f"(d1), "+f"(d2), "+f"(d3)
                 : "r"(a0), "r"(a1), "r"(a2), "r"(a3), "r"(b0), "r"(b1));
}

// C[N,384] = A[N,K] @ W[K,384], double-buffered smem (1 sync / k-chunk).
// MODE 1: epilogue -> g_h1; MODE 2: epilogue -> g_lin / g_m2h / g_cprod
template <int MODE>
__global__ __launch_bounds__(256, 2) void k_gemm_tc(
    int N,
    const float* __restrict__ bL1, const float* __restrict__ bR1,
    const float* __restrict__ bL2, const float* __restrict__ bR2,
    const float* __restrict__ bng, const float* __restrict__ bnb,
    const float* __restrict__ bnm, const float* __restrict__ bnv) {
    constexpr int K = (MODE == 1) ? 64 : 192;
    constexpr int NK = K / 8;
    const float* __restrict__ A = (MODE == 1) ? g_xa : g_h1;
    const float* __restrict__ W = (MODE == 1) ? g_W1 : g_W2;

    __shared__ uint32_t As[2][128 * 12];
    __shared__ uint32_t Ws[2][128 * 12];

    const int rowBase = blockIdx.x * 128;
    const int s = blockIdx.y;          // col slice 0..2
    const int colBase = s * 128;
    const int tid = threadIdx.x;
    const int warp = tid >> 5, lane = tid & 31;
    const int wm = warp >> 2, wn = warp & 3;
    const int gq = lane >> 2, tq = lane & 3;

    float acc[4][4][4];
#pragma unroll
    for (int i = 0; i < 4; i++)
#pragma unroll
        for (int j = 0; j < 4; j++)
#pragma unroll
            for (int c = 0; c < 4; c++) acc[i][j][c] = 0.f;

    const int ar = tid >> 1, ah = tid & 1;
    const int wc = tid & 127, wkp = tid >> 7;
    int gr = rowBase + ar;
    if (gr >= N) gr = N - 1;
    const float* Arow = A + (size_t)gr * K + ah * 4;
    const float* Wcol = W + colBase + wc;

    // prologue: stage chunk 0 -> buffer 0
    {
        float4 av = *(const float4*)(Arow);
        uint32_t* ad = &As[0][ar * 12 + ah * 4];
        ad[0] = f2tf32(av.x); ad[1] = f2tf32(av.y);
        ad[2] = f2tf32(av.z); ad[3] = f2tf32(av.w);
#pragma unroll
        for (int i = 0; i < 4; i++)
            Ws[0][wc * 12 + wkp * 4 + i] = f2tf32(Wcol[(size_t)(wkp * 4 + i) * 384]);
    }
    __syncthreads();

    for (int kc = 0; kc < NK; kc++) {
        const int cur = kc & 1;
        float4 av;
        float wv[4];
        const bool more = (kc + 1 < NK);
        if (more) {
            av = *(const float4*)(Arow + (kc + 1) * 8);
#pragma unroll
            for (int i = 0; i < 4; i++)
                wv[i] = Wcol[(size_t)((kc + 1) * 8 + wkp * 4 + i) * 384];
        }

        uint32_t af[4][4], bf[4][2];
#pragma unroll
        for (int i = 0; i < 4; i++) {
            int m0 = wm * 64 + i * 16;
            af[i][0] = As[cur][(m0 + gq) * 12 + tq];
            af[i][1] = As[cur][(m0 + gq + 8) * 12 + tq];
            af[i][2] = As[cur][(m0 + gq) * 12 + tq + 4];
            af[i][3] = As[cur][(m0 + gq + 8) * 12 + tq + 4];
        }
#pragma unroll
        for (int j = 0; j < 4; j++) {
            int n0 = ((j < 2) ? 0 : 64) + wn * 16 + (j & 1) * 8;
            bf[j][0] = Ws[cur][(n0 + gq) * 12 + tq];
            bf[j][1] = Ws[cur][(n0 + gq) * 12 + tq + 4];
        }
#pragma unroll
        for (int i = 0; i < 4; i++)
#pragma unroll
            for (int j = 0; j < 4; j++)
                mma_tf32(acc[i][j][0], acc[i][j][1], acc[i][j][2], acc[i][j][3],
                         af[i][0], af[i][1], af[i][2], af[i][3],
                         bf[j][0], bf[j][1]);

        if (more) {
            uint32_t* ad = &As[cur ^ 1][ar * 12 + ah * 4];
            ad[0] = f2tf32(av.x); ad[1] = f2tf32(av.y);
            ad[2] = f2tf32(av.z); ad[3] = f2tf32(av.w);
#pragma unroll
            for (int i = 0; i < 4; i++)
                Ws[cur ^ 1][wc * 12 + wkp * 4 + i] = f2tf32(wv[i]);
        }
        __syncthreads();
    }

    // fused epilogue: pairs are (acc[i][j][*], acc[i][j+2][*]) for j=0,1
#pragma unroll
    for (int i = 0; i < 4; i++) {
#pragma unroll
        for (int j = 0; j < 2; j++) {
            int l = wn * 16 + j * 8 + tq * 2;  // local col in [0,64)
#pragma unroll
            for (int p = 0; p < 2; p++) {
                int n = rowBase + wm * 64 + i * 16 + gq + p * 8;
                if (n >= N) continue;
                float o0, o1;
                if (s < 2) {
                    int ch = s * 64 + l;
                    float L0 = acc[i][j][p * 2 + 0], L1 = acc[i][j][p * 2 + 1];
                    float R0 = acc[i][j + 2][p * 2 + 0], R1 = acc[i][j + 2][p * 2 + 1];
                    if (MODE == 1) {
                        float v0 = fmaxf(L0 + __ldg(&bL1[ch]), 0.f) +
                                   fmaxf(R0 + __ldg(&bR1[ch]), 0.f);
                        float v1 = fmaxf(L1 + __ldg(&bL1[ch + 1]), 0.f) +
                                   fmaxf(R1 + __ldg(&bR1[ch + 1]), 0.f);
                        o0 = __ldg(&bng[ch]) * (v0 - __ldg(&bnm[ch])) *
                                 rsqrtf(__ldg(&bnv[ch]) + 1e-5f) + __ldg(&bnb[ch]);
                        o1 = __ldg(&bng[ch + 1]) * (v1 - __ldg(&bnm[ch + 1])) *
                                 rsqrtf(__ldg(&bnv[ch + 1]) + 1e-5f) + __ldg(&bnb[ch + 1]);
                        *(float2*)(g_h1 + (size_t)n * 192 + ch) = make_float2(o0, o1);
                    } else {
                        float r0 = fmaxf(L0 + __ldg(&bL1[ch]), 0.f);
                        float r1 = fmaxf(L1 + __ldg(&bL1[ch + 1]), 0.f);
                        *(float2*)(g_lin + (size_t)n * 128 + ch) = make_float2(r0, r1);
                        *(__nv_bfloat162*)(g_m2h + (size_t)n * 128 + ch) =
                            __floats2bfloat162_rn(R0, R1);
                    }
                } else {
                    float L0 = acc[i][j][p * 2 + 0], L1 = acc[i][j][p * 2 + 1];
                    float R0 = acc[i][j + 2][p * 2 + 0], R1 = acc[i][j + 2][p * 2 + 1];
                    float v0 = fmaxf(L0 + __ldg(&bL2[l]), 0.f) *
                               fmaxf(R0 + __ldg(&bR2[l]), 0.f);
                    float v1 = fmaxf(L1 + __ldg(&bL2[l + 1]), 0.f) *
                               fmaxf(R1 + __ldg(&bR2[l + 1]), 0.f);
                    if (MODE == 1) {
                        int ch = 128 + l;
                        o0 = __ldg(&bng[ch]) * (v0 - __ldg(&bnm[ch])) *
                                 rsqrtf(__ldg(&bnv[ch]) + 1e-5f) + __ldg(&bnb[ch]);
                        o1 = __ldg(&bng[ch + 1]) * (v1 - __ldg(&bnm[ch + 1])) *
                                 rsqrtf(__ldg(&bnv[ch + 1]) + 1e-5f) + __ldg(&bnb[ch + 1]);
                        *(float2*)(g_h1 + (size_t)n * 192 + ch) = make_float2(o0, o1);
                    } else {
                        *(float2*)(g_cprod + (size_t)n * 64 + l) = make_float2(v0, v1);
                    }
                }
            }
        }
    }
}

// Fused: agg2[v] = sum_{u->v} m2h[u] (bf16 gather, fp32 acc, unroll 4)
// + block-2 epilogue -> h2  (R13-proven single-warp form)
__global__ void k_agg2_ep2(const float* __restrict__ conv21_b,
                           const float* __restrict__ gg, const float* __restrict__ bb,
                           const float* __restrict__ mm, const float* __restrict__ vv,
                           int N) {
    int w = (blockIdx.x * blockDim.x + threadIdx.x) >> 5;
    int lane = threadIdx.x & 31;
    if (w >= N) return;
    int e0 = g_rowptr[w], e1 = g_rowptr[w + 1];
    float a0 = 0.f, a1 = 0.f, a2 = 0.f, a3 = 0.f;
    int e = e0;
    for (; e + 4 <= e1; e += 4) {
        int s0 = g_col[e], s1 = g_col[e + 1], s2 = g_col[e + 2], s3 = g_col[e + 3];
        uint2 u0 = *(const uint2*)(g_m2h + (size_t)s0 * 128 + lane * 4);
        uint2 u1 = *(const uint2*)(g_m2h + (size_t)s1 * 128 + lane * 4);
        uint2 u2 = *(const uint2*)(g_m2h + (size_t)s2 * 128 + lane * 4);
        uint2 u3 = *(const uint2*)(g_m2h + (size_t)s3 * 128 + lane * 4);
#pragma unroll
        for (int q = 0; q < 4; q++) {
            uint2 u = (q == 0) ? u0 : (q == 1) ? u1 : (q == 2) ? u2 : u3;
            float2 lo = __bfloat1622float2(*(__nv_bfloat162*)&u.x);
            float2 hi = __bfloat1622float2(*(__nv_bfloat162*)&u.y);
            a0 += lo.x; a1 += lo.y; a2 += hi.x; a3 += hi.y;
        }
    }
    for (; e < e1; e++) {
        int sc = g_col[e];
        uint2 u = *(const uint2*)(g_m2h + (size_t)sc * 128 + lane * 4);
        float2 lo = __bfloat1622float2(*(__nv_bfloat162*)&u.x);
        float2 hi = __bfloat1622float2(*(__nv_bfloat162*)&u.y);
        a0 += lo.x; a1 += lo.y; a2 += hi.x; a3 += hi.y;
    }
    int c0 = lane * 4;
    float4 lb = *(const float4*)(g_lin + (size_t)w * 128 + c0);
    float4 cb = *(const float4*)(conv21_b + c0);
    float v0 = lb.x + fmaxf(a0 + cb.x, 0.f);
    float v1 = lb.y + fmaxf(a1 + cb.y, 0.f);
    float v2 = lb.z + fmaxf(a2 + cb.z, 0.f);
    float v3 = lb.w + fmaxf(a3 + cb.w, 0.f);
    float4 G = *(const float4*)(gg + c0);
    float4 B = *(const float4*)(bb + c0);
    float4 M = *(const float4*)(mm + c0);
    float4 V = *(const float4*)(vv + c0);
    float4 o;
    o.x = G.x * (v0 - M.x) * rsqrtf(V.x + 1e-5f) + B.x;
    o.y = G.y * (v1 - M.y) * rsqrtf(V.y + 1e-5f) + B.y;
    o.z = G.z * (v2 - M.z) * rsqrtf(V.z + 1e-5f) + B.z;
    o.w = G.w * (v3 - M.w) * rsqrtf(V.w + 1e-5f) + B.w;
    *(float4*)(g_h2 + (size_t)w * 192 + c0) = o;
    if (lane < 16) {
        int l = lane * 4, ch = 128 + l;
        float4 cp = *(const float4*)(g_cprod + (size_t)w * 64 + l);
        float4 G2 = *(const float4*)(gg + ch);
        float4 B2 = *(const float4*)(bb + ch);
        float4 M2 = *(const float4*)(mm + ch);
        float4 V2 = *(const float4*)(vv + ch);
        float4 o2;
        o2.x = G2.x * (cp.x - M2.x) * rsqrtf(V2.x + 1e-5f) + B2.x;
        o2.y = G2.y * (cp.y - M2.y) * rsqrtf(V2.y + 1e-5f) + B2.y;
        o2.z = G2.z * (cp.z - M2.z) * rsqrtf(V2.z + 1e-5f) + B2.z;
        o2.w = G2.w * (cp.w - M2.w) * rsqrtf(V2.w + 1e-5f) + B2.w;
        *(float4*)(g_h2 + (size_t)w * 192 + ch) = o2;
    }
}

// ---------------- fused pooling + head (batch is sorted) ----------------
__device__ __forceinline__ int lb_batch(const void* batch, int n, long long val) {
    int lo = 0, hi = n;
    while (lo < hi) {
        int mid = (lo + hi) >> 1;
        long long b = g_is64 ? ((const long long*)batch)[mid]
                             : (long long)((const int*)batch)[mid];
        if (b < val) lo = mid + 1; else hi = mid;
    }
    return lo;
}

__global__ void k_poolhead(const void* batch, int N,
                           const float* __restrict__ w2, const float* __restrict__ b2,
                           float* __restrict__ out) {
    int g = blockIdx.x;
    __shared__ int slo, shi;
    __shared__ float spool[384];
    __shared__ float cls[6][6];
    int tid = threadIdx.x;
    if (tid == 0) {
        slo = lb_batch(batch, N, (long long)g);
        shi = lb_batch(batch, N, (long long)g + 1);
    }
    __syncthreads();
    int lo = slo, hi = shi;
    float sum = 0.f, mx = -3.402823466e38f;
    for (int n = lo; n < hi; n++) {
        float v = g_h2[(size_t)n * 192 + tid];
        sum += v;
        mx = fmaxf(mx, v);
    }
    int cnt = hi - lo;
    spool[tid] = sum / fmaxf((float)cnt, 1.f);
    spool[192 + tid] = (cnt > 0) ? mx : 0.f;
    __syncthreads();

    float p[6] = {0.f, 0.f, 0.f, 0.f, 0.f, 0.f};
#pragma unroll
    for (int h = 0; h < 2; h++) {
        int kk = tid + h * 192;
        float gv = spool[kk];
#pragma unroll
        for (int j = 0; j < 6; j++) p[j] += gv * __ldg(&w2[kk * 6 + j]);
    }
    int lane = tid & 31, warp = tid >> 5;
#pragma unroll
    for (int off = 16; off; off >>= 1)
#pragma unroll
        for (int j = 0; j < 6; j++) p[j] += __shfl_xor_sync(0xffffffffu, p[j], off);
    if (lane == 0)
#pragma unroll
        for (int j = 0; j < 6; j++) cls[j][warp] = p[j];
    __syncthreads();
    if (tid == 0) {
        float v[6];
        float mxv = -3.402823466e38f;
#pragma unroll
        for (int j = 0; j < 6; j++) {
            float acc = b2[j];
#pragma unroll
            for (int q = 0; q < 6; q++) acc += cls[j][q];
            v[j] = acc;
            mxv = fmaxf(mxv, acc);
        }
        float ssum = 0.f;
#pragma unroll
        for (int j = 0; j < 6; j++) ssum += expf(v[j] - mxv);
        float lse = mxv + logf(ssum);
#pragma unroll
        for (int j = 0; j < 6; j++) out[g * 6 + j] = v[j] - lse;
    }
}

// ---------------- launch ----------------
extern "C" void kernel_launch(void* const* d_in, const int* in_sizes, int n_in,
                              void* d_out, int out_size) {
    int base = (n_in >= 30) ? 4 : 3;
    const float* x        = (const float*)d_in[0];
    const void*  ei       = d_in[1];
    const void*  batch    = d_in[2];
    const float* fc11_w   = (const float*)d_in[base + 0];
    const float* fc11_b   = (const float*)d_in[base + 1];
    const float* conv11_w = (const float*)d_in[base + 2];
    const float* conv11_b = (const float*)d_in[base + 3];
    const float* fc12_w   = (const float*)d_in[base + 4];
    const float* fc12_b   = (const float*)d_in[base + 5];
    const float* fc13_w   = (const float*)d_in[base + 6];
    const float* fc13_b   = (const float*)d_in[base + 7];
    const float* bn1_g    = (const float*)d_in[base + 8];
    const float* bn1_b    = (const float*)d_in[base + 9];
    const float* bn1_m    = (const float*)d_in[base + 10];
    const float* bn1_v    = (const float*)d_in[base + 11];
    const float* fc21_w   = (const float*)d_in[base + 12];
    const float* fc21_b   = (const float*)d_in[base + 13];
    const float* conv21_w = (const float*)d_in[base + 14];
    const float* conv21_b = (const float*)d_in[base + 15];
    const float* fc22_w   = (const float*)d_in[base + 16];
    const float* fc22_b   = (const float*)d_in[base + 17];
    const float* fc23_w   = (const float*)d_in[base + 18];
    const float* fc23_b   = (const float*)d_in[base + 19];
    const float* bn2_g    = (const float*)d_in[base + 20];
    const float* bn2_b    = (const float*)d_in[base + 21];
    const float* bn2_m    = (const float*)d_in[base + 22];
    const float* bn2_v    = (const float*)d_in[base + 23];
    const float* fc2_w    = (const float*)d_in[base + 24];
    const float* fc2_b    = (const float*)d_in[base + 25];

    int N = in_sizes[0] / 32;
    int E = in_sizes[1] / 2;
    int G = out_size / 6;
    float* out = (float*)d_out;

    // fused init+hist, two-kernel scan, per-edge fill
    int initN = N * 32;
    if (initN < E) initN = E;
    if (initN < 192 * 384) initN = 192 * 384;
    k_init<<<(initN + 255) / 256, 256>>>((const unsigned int*)ei, x,
                                         fc11_w, conv11_w, fc12_w, fc13_w,
                                         fc21_w, conv21_w, fc22_w, fc23_w, N, E);
    int nb = (N + 1023) / 1024;
    k_scan_a<<<nb, 1024>>>(N);
    k_scan_c<<<(N + 255) / 256, 256>>>(N, E);
    k_fill<<<(E + 255) / 256, 256>>>(ei, E);

    // block 1
    k_agg1<<<(N * 32 + 255) / 256, 256>>>(x, N);
    dim3 gg((N + 127) / 128, 3);
    k_gemm_tc<1><<<gg, 256>>>(N, fc11_b, conv11_b, fc12_b, fc13_b,
                              bn1_g, bn1_b, bn1_m, bn1_v);

    // block 2
    k_gemm_tc<2><<<gg, 256>>>(N, fc21_b, conv21_b, fc22_b, fc23_b,
                              bn2_g, bn2_b, bn2_m, bn2_v);
    k_agg2_ep2<<<(N * 32 + 255) / 256, 256>>>(conv21_b, bn2_g, bn2_b, bn2_m, bn2_v, N);

    // fused pooling + head
    k_poolhead<<<G, 192>>>(batch, N, fc2_w, fc2_b, out);
}